// round 13
// baseline (speedup 1.0000x reference)
#include <cuda_runtime.h>
#include <cstdint>
#include <cfloat>

// RandomProjectionQuantizer (R12): fast projection + split-K FFMA2 scoring.
//   xp = x @ P    (normalization skipped: positive row scale preserves argmax)
//   out[i] = (float) argmax_j xp_i . CB_j      <- FLOAT output
//
// R12 change: proj_quad replaces proj_pairs. 4 threads/row, 256 CTAs, no
// inner-loop barriers, direct global float4 streaming of x, P in smem once,
// shfl-combine. (R11 proj was 64us at occ 6.3% from barrier ping-pong.)
// K2 (FFMA2 row-pair scoring) and K3 unchanged.

#define THREADS      256
#define CHUNK        256
#define SPLITS       32
#define MAXN         16384
#define MAXV         8192
#define MAXD         512

// ---------------- scratch ----------------
__device__ __align__(16) float g_xp2[MAXN * 16];        // 1 MB pair-interleaved
__device__ float g_pval[SPLITS * MAXN];                 // 2 MB
__device__ int   g_pidx[SPLITS * MAXN];                 // 2 MB

// ---------------- f32x2 helpers ----------------
__device__ __forceinline__ unsigned long long splat2(float x) {
    unsigned long long r; unsigned int b = __float_as_uint(x);
    asm("mov.b64 %0, {%1, %1};" : "=l"(r) : "r"(b));
    return r;
}
__device__ __forceinline__ unsigned long long fma2(unsigned long long a,
                                                   unsigned long long b,
                                                   unsigned long long c) {
    unsigned long long d;
    asm("fma.rn.f32x2 %0, %1, %2, %3;" : "=l"(d) : "l"(a), "l"(b), "l"(c));
    return d;
}
__device__ __forceinline__ unsigned long long add2(unsigned long long a,
                                                   unsigned long long b) {
    unsigned long long d;
    asm("add.rn.f32x2 %0, %1, %2;" : "=l"(d) : "l"(a), "l"(b));
    return d;
}

// ============================================================================
// K1 (R12): projection, 4 threads per row, 64 rows/CTA, 256 threads.
// x streamed directly from global (float4, unrolled -> MLP); P in smem once;
// quarter-sums combined via shfl_xor; output pair-interleaved into g_xp2.
// Requires: D % 16 == 0, D <= 512, N % 64 == 0.
// ============================================================================
__global__ __launch_bounds__(256)
void proj_quad(const float* __restrict__ x, const float* __restrict__ P,
               int N, int D) {
    __shared__ __align__(16) float Ps[MAXD * 16];       // 32 KB max

    const int t   = threadIdx.x;
    const int r   = t >> 2;                // local row 0..63
    const int q   = t & 3;                 // quarter 0..3
    const int row = blockIdx.x * 64 + r;
    const int D4  = D >> 2;

    // stage P (whole matrix), float4 coalesced
    const int np4 = (D * 16) >> 2;
    for (int i = t; i < np4; i += 256)
        ((float4*)Ps)[i] = ((const float4*)P)[i];
    __syncthreads();

    float acc[16];
#pragma unroll
    for (int i = 0; i < 16; i++) acc[i] = 0.0f;

    const float4* xr = (const float4*)(x + (long long)row * D + q * D4);
    const int dbase0 = q * D4;

#pragma unroll 4
    for (int c = 0; c < D4 / 4; c++) {
        float4 xa = xr[c];
        const int db = dbase0 + c * 4;
#pragma unroll
        for (int u = 0; u < 4; u++) {
            float xv = (u == 0) ? xa.x : (u == 1) ? xa.y : (u == 2) ? xa.z : xa.w;
            const float4* pr = (const float4*)&Ps[(db + u) * 16];
            float4 p0 = pr[0], p1 = pr[1], p2 = pr[2], p3 = pr[3];
            acc[0]  = fmaf(xv, p0.x, acc[0]);  acc[1]  = fmaf(xv, p0.y, acc[1]);
            acc[2]  = fmaf(xv, p0.z, acc[2]);  acc[3]  = fmaf(xv, p0.w, acc[3]);
            acc[4]  = fmaf(xv, p1.x, acc[4]);  acc[5]  = fmaf(xv, p1.y, acc[5]);
            acc[6]  = fmaf(xv, p1.z, acc[6]);  acc[7]  = fmaf(xv, p1.w, acc[7]);
            acc[8]  = fmaf(xv, p2.x, acc[8]);  acc[9]  = fmaf(xv, p2.y, acc[9]);
            acc[10] = fmaf(xv, p2.z, acc[10]); acc[11] = fmaf(xv, p2.w, acc[11]);
            acc[12] = fmaf(xv, p3.x, acc[12]); acc[13] = fmaf(xv, p3.y, acc[13]);
            acc[14] = fmaf(xv, p3.z, acc[14]); acc[15] = fmaf(xv, p3.w, acc[15]);
        }
    }

    // combine the 4 quarter-sums (lanes differ in bits 0-1 of lane id)
#pragma unroll
    for (int i = 0; i < 16; i++) {
        acc[i] += __shfl_xor_sync(0xFFFFFFFFu, acc[i], 1);
        acc[i] += __shfl_xor_sync(0xFFFFFFFFu, acc[i], 2);
    }

    // lane q writes dims 4q..4q+3, pair-interleaved:
    // g_xp2[(row>>1)*32 + 2k + (row&1)] = xp[row][k]
    float* dst = g_xp2 + (row >> 1) * 32 + (row & 1);
#pragma unroll
    for (int u = 0; u < 4; u++) {
        int k = 4 * q + u;
        dst[2 * k] = acc[k];
    }
}

// ============================================================================
// K2: split-K argmax partials with FFMA2. grid = (rowpairs/256, SPLITS).
// ============================================================================
__global__ __launch_bounds__(THREADS)
void argmax_partial(const float* __restrict__ CB, int N, int V) {
    __shared__ __align__(16) unsigned long long cbs[CHUNK][16];   // 32 KB

    const int t = threadIdx.x;
    const int code0 = blockIdx.y * CHUNK;

#pragma unroll 4
    for (int q = t; q < CHUNK * 16; q += THREADS) {
        float c = CB[(long long)(code0 + (q >> 4)) * 16 + (q & 15)];
        cbs[q >> 4][q & 15] = splat2(c);
    }

    const int rp = blockIdx.x * THREADS + t;
    const ulonglong2* xg = (const ulonglong2*)(g_xp2 + (long long)rp * 32);
    unsigned long long xp[16];
#pragma unroll
    for (int i = 0; i < 8; i++) { ulonglong2 v = xg[i]; xp[2 * i] = v.x; xp[2 * i + 1] = v.y; }

    __syncthreads();

    float best0 = -FLT_MAX, best1 = -FLT_MAX;
    int idx0 = 0, idx1 = 0;

#pragma unroll 2
    for (int j = 0; j < CHUNK; j++) {
        const ulonglong2* cp = (const ulonglong2*)&cbs[j][0];     // broadcast LDS.128
        unsigned long long a = 0ULL, b = 0ULL;
#pragma unroll
        for (int i = 0; i < 8; i++) {
            ulonglong2 c = cp[i];
            a = fma2(xp[2 * i],     c.x, a);
            b = fma2(xp[2 * i + 1], c.y, b);
        }
        union { unsigned long long u; float f[2]; } s; s.u = add2(a, b);
        if (s.f[0] > best0) { best0 = s.f[0]; idx0 = j; }         // strict >: first max
        if (s.f[1] > best1) { best1 = s.f[1]; idx1 = j; }
    }

    const long long off = (long long)blockIdx.y * N + (long long)rp * 2;
    g_pval[off]     = best0;  g_pidx[off]     = code0 + idx0;
    g_pval[off + 1] = best1;  g_pidx[off + 1] = code0 + idx1;
}

// ============================================================================
// K3: reduce partials; ascending split + strict > = global first-max. Float out.
// ============================================================================
__global__ __launch_bounds__(256)
void argmax_reduce(float* __restrict__ out, int N, int nsplit) {
    const int row = blockIdx.x * 256 + threadIdx.x;
    if (row >= N) return;
    float best = -FLT_MAX;
    int bi = 0;
    for (int s = 0; s < nsplit; s++) {
        float v = g_pval[(long long)s * N + row];
        if (v > best) { best = v; bi = g_pidx[(long long)s * N + row]; }
    }
    out[row] = (float)bi;
}

// ============================================================================
// Fallbacks (proven R10 kernels) for any other shape.
// ============================================================================
union SMemF {
    struct { __align__(16) float xs[128][33]; __align__(16) float Ps[32][16]; } p1;
    __align__(16) float cbs[CHUNK][16];
    struct { float sv[THREADS]; int si[THREADS]; } p3;
};

__global__ __launch_bounds__(THREADS)
void rpq_fused16(const float* __restrict__ x, const float* __restrict__ P,
                 const float* __restrict__ CB, float* __restrict__ out,
                 int N, int D, int V) {
    __shared__ SMemF sm;
    const int t = threadIdx.x;
    const int rl = t & 127;
    const int half = t >> 7;
    const int row0 = blockIdx.x * 128;

    float acc[16];
#pragma unroll
    for (int i = 0; i < 16; i++) acc[i] = 0.0f;

    const int nkc = (D + 31) >> 5;
    for (int kc = 0; kc < nkc; kc++) {
#pragma unroll
        for (int q = t; q < 128 * 32; q += THREADS) {
            int r = q >> 5, c = q & 31;
            int row = row0 + r, d = kc * 32 + c;
            sm.p1.xs[r][c] = (row < N && d < D) ? x[(long long)row * D + d] : 0.0f;
        }
#pragma unroll
        for (int q = t; q < 32 * 16; q += THREADS) {
            int k = q >> 4, i = q & 15;
            int d = kc * 32 + k;
            sm.p1.Ps[k][i] = (d < D) ? P[(long long)d * 16 + i] : 0.0f;
        }
        __syncthreads();
#pragma unroll 4
        for (int k = 0; k < 32; k++) {
            float xv = sm.p1.xs[rl][k];
            const float4* pr = (const float4*)&sm.p1.Ps[k][0];
#pragma unroll
            for (int i4 = 0; i4 < 4; i4++) {
                float4 p = pr[i4];
                acc[4 * i4]     = fmaf(xv, p.x, acc[4 * i4]);
                acc[4 * i4 + 1] = fmaf(xv, p.y, acc[4 * i4 + 1]);
                acc[4 * i4 + 2] = fmaf(xv, p.z, acc[4 * i4 + 2]);
                acc[4 * i4 + 3] = fmaf(xv, p.w, acc[4 * i4 + 3]);
            }
        }
        __syncthreads();
    }

    float best = -FLT_MAX; int bi = 0x7FFFFFFF;
    for (int c0 = 0; c0 < V; c0 += CHUNK) {
        const int cnt = (V - c0 < CHUNK) ? (V - c0) : CHUNK;
#pragma unroll
        for (int q = t; q < CHUNK * 16; q += THREADS) {
            int j = q >> 4, i = q & 15;
            sm.cbs[j][i] = (j < cnt) ? CB[(long long)(c0 + j) * 16 + i] : 0.0f;
        }
        __syncthreads();
        const int jbase = half * 128;
#pragma unroll 2
        for (int jj = 0; jj < 128; jj++) {
            const int j = jbase + jj;
            const float4* cb = (const float4*)&sm.cbs[j][0];
            float s0 = 0, s1 = 0, s2 = 0, s3 = 0;
#pragma unroll
            for (int i4 = 0; i4 < 4; i4++) {
                float4 c = cb[i4];
                s0 = fmaf(acc[4 * i4],     c.x, s0);
                s1 = fmaf(acc[4 * i4 + 1], c.y, s1);
                s2 = fmaf(acc[4 * i4 + 2], c.z, s2);
                s3 = fmaf(acc[4 * i4 + 3], c.w, s3);
            }
            float s = (s0 + s1) + (s2 + s3);
            if (c0 + j < V && s > best) { best = s; bi = c0 + j; }
        }
        __syncthreads();
    }

    sm.p3.sv[t] = best; sm.p3.si[t] = bi;
    __syncthreads();
    if (t < 128) {
        int row = row0 + t;
        if (row < N) {
            float slo = sm.p3.sv[t], shi = sm.p3.sv[t + 128];
            int   ilo = sm.p3.si[t], ihi = sm.p3.si[t + 128];
            int win = (shi > slo || (shi == slo && ihi < ilo)) ? ihi : ilo;
            out[row] = (float)win;
        }
    }
}

__global__ void rpq_generic(const float* __restrict__ x, const float* __restrict__ P,
                            const float* __restrict__ CB, float* __restrict__ out,
                            int N, int D, int V, int cbd) {
    int row = blockIdx.x * blockDim.x + threadIdx.x;
    if (row >= N) return;
    float acc[64];
    for (int i = 0; i < cbd; i++) acc[i] = 0.0f;
    for (int d = 0; d < D; d++) {
        float xv = x[(long long)row * D + d];
        for (int i = 0; i < cbd; i++) acc[i] = fmaf(xv, P[(long long)d * cbd + i], acc[i]);
    }
    float best = -FLT_MAX; int bi = 0;
    for (int j = 0; j < V; j++) {
        float s = 0.0f;
        for (int i = 0; i < cbd; i++) s = fmaf(acc[i], CB[(long long)j * cbd + i], s);
        if (s > best) { best = s; bi = j; }
    }
    out[row] = (float)bi;
}

// ============================================================================
extern "C" void kernel_launch(void* const* d_in, const int* in_sizes, int n_in,
                              void* d_out, int out_size) {
    const float* x  = (const float*)d_in[0];
    const float* P  = (n_in > 1) ? (const float*)d_in[1] : nullptr;
    const float* CB = (n_in > 2) ? (const float*)d_in[2] : nullptr;
    long long N = out_size, D = 512, CBD = 16, V = 8192;

    if (n_in >= 3 && out_size > 0) {
        int order[3] = {0, 1, 2};
        for (int a = 0; a < 2; a++)
            for (int b = a + 1; b < 3; b++)
                if ((long long)in_sizes[order[b]] > (long long)in_sizes[order[a]]) {
                    int tmp = order[a]; order[a] = order[b]; order[b] = tmp;
                }
        long long sx = in_sizes[order[0]];
        long long sc = in_sizes[order[1]];
        long long sp = in_sizes[order[2]];
        if (sx % N == 0) {
            long long d = sx / N;
            if (d > 0 && sp % d == 0) {
                long long cbd = sp / d;
                if (cbd > 0 && cbd <= 64 && sc % cbd == 0) {
                    long long v = sc / cbd;
                    if (v > 0 && d * cbd == sp && v * cbd == sc && N * d == sx) {
                        D = d; CBD = cbd; V = v;
                        x  = (const float*)d_in[order[0]];
                        CB = (const float*)d_in[order[1]];
                        P  = (const float*)d_in[order[2]];
                    }
                }
            }
        }
    }

    float* out = (float*)d_out;
    int Ni = (int)N, Di = (int)D, Vi = (int)V;

    const bool fast = (CBD == 16) && (Ni % 512 == 0) && (Vi % CHUNK == 0) &&
                      (Di % 16 == 0) && (Di <= MAXD) && (Ni <= MAXN) &&
                      (Vi <= MAXV) && ((Vi / CHUNK) <= SPLITS) && (Vi >= CHUNK);

    if (fast) {
        const int nsplit    = Vi / CHUNK;
        const int rowpairs  = Ni / 2;
        const int rowblocks = rowpairs / THREADS;    // Ni % 512 == 0 -> integer
        proj_quad<<<Ni / 64, 256>>>(x, P, Ni, Di);
        argmax_partial<<<dim3(rowblocks, nsplit), THREADS>>>(CB, Ni, Vi);
        argmax_reduce<<<(Ni + 255) / 256, 256>>>(out, Ni, nsplit);
        return;
    }

    if (CBD == 16) {
        rpq_fused16<<<(Ni + 127) / 128, THREADS>>>(x, P, CB, out, Ni, Di, Vi);
    } else {
        rpq_generic<<<(Ni + 255) / 256, 256>>>(x, P, CB, out, Ni, Di, Vi, (int)CBD);
    }
}

// round 14
// speedup vs baseline: 1.2547x; 1.2547x over previous
#include <cuda_runtime.h>
#include <cstdint>
#include <cfloat>

// RandomProjectionQuantizer (R13): split-D projection + split-K FFMA2 scoring.
//   xp = x @ P    (normalization skipped: positive row scale preserves argmax)
//   out[i] = (float) argmax_j xp_i . CB_j      <- FLOAT output
//
// R13: proj_splitD replaces proj_quad (R12 regression: non-uniform LDS ->
// bank conflicts, L1=78%). Thread-owns-row => warp-uniform P broadcast;
// grid (N/128 rowblocks x 2 D-halves) = 256 CTAs, no inner barriers;
// halves write g_xpA/g_xpB, K2 sums them at load. K2/K3 unchanged.

#define THREADS      256
#define CHUNK        256
#define SPLITS       32
#define MAXN         16384
#define MAXV         8192
#define MAXD         512

// ---------------- scratch ----------------
__device__ __align__(16) float g_xpA[MAXN * 16];        // 1 MB pair-interleaved
__device__ __align__(16) float g_xpB[MAXN * 16];        // 1 MB pair-interleaved
__device__ float g_pval[SPLITS * MAXN];                 // 2 MB
__device__ int   g_pidx[SPLITS * MAXN];                 // 2 MB

// ---------------- f32x2 helpers ----------------
__device__ __forceinline__ unsigned long long splat2(float x) {
    unsigned long long r; unsigned int b = __float_as_uint(x);
    asm("mov.b64 %0, {%1, %1};" : "=l"(r) : "r"(b));
    return r;
}
__device__ __forceinline__ unsigned long long fma2(unsigned long long a,
                                                   unsigned long long b,
                                                   unsigned long long c) {
    unsigned long long d;
    asm("fma.rn.f32x2 %0, %1, %2, %3;" : "=l"(d) : "l"(a), "l"(b), "l"(c));
    return d;
}
__device__ __forceinline__ unsigned long long add2(unsigned long long a,
                                                   unsigned long long b) {
    unsigned long long d;
    asm("add.rn.f32x2 %0, %1, %2;" : "=l"(d) : "l"(a), "l"(b));
    return d;
}

// ============================================================================
// K1 (R13): split-D projection. grid = (N/128, 2). 128 threads, 1 row each.
// CTA (b, s): rows [b*128, b*128+128), dims [s*D/2, (s+1)*D/2).
// P-half staged to smem once; inner loop has NO barriers; P reads are
// warp-uniform (all lanes at same d) -> LDS broadcast, conflict-free.
// x read per-thread from global as float4 (line reuse across 8 d -> L1 hits).
// Output: partial xp, pair-interleaved, into g_xpA (s=0) / g_xpB (s=1).
// Requires D % 32 == 0, D <= MAXD, N % 128 == 0.
// ============================================================================
__global__ __launch_bounds__(128)
void proj_splitD(const float* __restrict__ x, const float* __restrict__ P,
                 int N, int D) {
    __shared__ __align__(16) float Ps[(MAXD / 2) * 16];   // 16 KB max

    const int t   = threadIdx.x;
    const int s   = blockIdx.y;                // D-half
    const int D2  = D >> 1;
    const int d0  = s * D2;
    const int row = blockIdx.x * 128 + t;

    // stage this half of P (D2 x 16 floats), float4-coalesced
    const int np4 = (D2 * 16) >> 2;
    const float4* Pg = (const float4*)(P + (long long)d0 * 16);
    for (int i = t; i < np4; i += 128)
        ((float4*)Ps)[i] = Pg[i];
    __syncthreads();

    float acc[16];
#pragma unroll
    for (int i = 0; i < 16; i++) acc[i] = 0.0f;

    const float4* xr = (const float4*)(x + (long long)row * D + d0);

#pragma unroll 2
    for (int c = 0; c < D2 / 4; c++) {
        float4 xa = xr[c];
#pragma unroll
        for (int u = 0; u < 4; u++) {
            float xv = (u == 0) ? xa.x : (u == 1) ? xa.y : (u == 2) ? xa.z : xa.w;
            const int d = c * 4 + u;                          // warp-uniform
            const float4* pr = (const float4*)&Ps[d * 16];    // broadcast LDS.128
            float4 p0 = pr[0], p1 = pr[1], p2 = pr[2], p3 = pr[3];
            acc[0]  = fmaf(xv, p0.x, acc[0]);  acc[1]  = fmaf(xv, p0.y, acc[1]);
            acc[2]  = fmaf(xv, p0.z, acc[2]);  acc[3]  = fmaf(xv, p0.w, acc[3]);
            acc[4]  = fmaf(xv, p1.x, acc[4]);  acc[5]  = fmaf(xv, p1.y, acc[5]);
            acc[6]  = fmaf(xv, p1.z, acc[6]);  acc[7]  = fmaf(xv, p1.w, acc[7]);
            acc[8]  = fmaf(xv, p2.x, acc[8]);  acc[9]  = fmaf(xv, p2.y, acc[9]);
            acc[10] = fmaf(xv, p2.z, acc[10]); acc[11] = fmaf(xv, p2.w, acc[11]);
            acc[12] = fmaf(xv, p3.x, acc[12]); acc[13] = fmaf(xv, p3.y, acc[13]);
            acc[14] = fmaf(xv, p3.z, acc[14]); acc[15] = fmaf(xv, p3.w, acc[15]);
        }
    }

    // pair-interleave: buf[(row>>1)*32 + 2k + (row&1)] = xp_partial[row][k]
    float* base = (s == 0) ? g_xpA : g_xpB;
    float* dst  = base + (row >> 1) * 32 + (row & 1);
#pragma unroll
    for (int k = 0; k < 16; k++) dst[2 * k] = acc[k];
}

// ============================================================================
// K2: split-K argmax partials with FFMA2; xp = g_xpA + g_xpB at load.
// grid = (rowpairs/256, SPLITS).
// ============================================================================
__global__ __launch_bounds__(THREADS)
void argmax_partial(const float* __restrict__ CB, int N, int V) {
    __shared__ __align__(16) unsigned long long cbs[CHUNK][16];   // 32 KB

    const int t = threadIdx.x;
    const int code0 = blockIdx.y * CHUNK;

#pragma unroll 4
    for (int q = t; q < CHUNK * 16; q += THREADS) {
        float c = CB[(long long)(code0 + (q >> 4)) * 16 + (q & 15)];
        cbs[q >> 4][q & 15] = splat2(c);
    }

    // sum the two projection halves for this row pair (32 floats)
    const int rp = blockIdx.x * THREADS + t;
    const float4* A = (const float4*)(g_xpA + (long long)rp * 32);
    const float4* B = (const float4*)(g_xpB + (long long)rp * 32);
    union { float f[32]; unsigned long long u[16]; } xp;
#pragma unroll
    for (int i = 0; i < 8; i++) {
        float4 a = A[i], b = B[i];
        xp.f[4 * i]     = a.x + b.x;
        xp.f[4 * i + 1] = a.y + b.y;
        xp.f[4 * i + 2] = a.z + b.z;
        xp.f[4 * i + 3] = a.w + b.w;
    }

    __syncthreads();

    float best0 = -FLT_MAX, best1 = -FLT_MAX;
    int idx0 = 0, idx1 = 0;

#pragma unroll 2
    for (int j = 0; j < CHUNK; j++) {
        const ulonglong2* cp = (const ulonglong2*)&cbs[j][0];     // broadcast LDS.128
        unsigned long long a = 0ULL, b = 0ULL;
#pragma unroll
        for (int i = 0; i < 8; i++) {
            ulonglong2 c = cp[i];
            a = fma2(xp.u[2 * i],     c.x, a);
            b = fma2(xp.u[2 * i + 1], c.y, b);
        }
        union { unsigned long long u; float f[2]; } sres; sres.u = add2(a, b);
        if (sres.f[0] > best0) { best0 = sres.f[0]; idx0 = j; }   // strict >: first max
        if (sres.f[1] > best1) { best1 = sres.f[1]; idx1 = j; }
    }

    const long long off = (long long)blockIdx.y * N + (long long)rp * 2;
    g_pval[off]     = best0;  g_pidx[off]     = code0 + idx0;
    g_pval[off + 1] = best1;  g_pidx[off + 1] = code0 + idx1;
}

// ============================================================================
// K3: reduce partials; ascending split + strict > = global first-max. Float out.
// ============================================================================
__global__ __launch_bounds__(256)
void argmax_reduce(float* __restrict__ out, int N, int nsplit) {
    const int row = blockIdx.x * 256 + threadIdx.x;
    if (row >= N) return;
    float best = -FLT_MAX;
    int bi = 0;
    for (int s = 0; s < nsplit; s++) {
        float v = g_pval[(long long)s * N + row];
        if (v > best) { best = v; bi = g_pidx[(long long)s * N + row]; }
    }
    out[row] = (float)bi;
}

// ============================================================================
// Fallbacks (proven R10 kernels) for any other shape.
// ============================================================================
union SMemF {
    struct { __align__(16) float xs[128][33]; __align__(16) float Ps[32][16]; } p1;
    __align__(16) float cbs[CHUNK][16];
    struct { float sv[THREADS]; int si[THREADS]; } p3;
};

__global__ __launch_bounds__(THREADS)
void rpq_fused16(const float* __restrict__ x, const float* __restrict__ P,
                 const float* __restrict__ CB, float* __restrict__ out,
                 int N, int D, int V) {
    __shared__ SMemF sm;
    const int t = threadIdx.x;
    const int rl = t & 127;
    const int half = t >> 7;
    const int row0 = blockIdx.x * 128;

    float acc[16];
#pragma unroll
    for (int i = 0; i < 16; i++) acc[i] = 0.0f;

    const int nkc = (D + 31) >> 5;
    for (int kc = 0; kc < nkc; kc++) {
#pragma unroll
        for (int q = t; q < 128 * 32; q += THREADS) {
            int r = q >> 5, c = q & 31;
            int row = row0 + r, d = kc * 32 + c;
            sm.p1.xs[r][c] = (row < N && d < D) ? x[(long long)row * D + d] : 0.0f;
        }
#pragma unroll
        for (int q = t; q < 32 * 16; q += THREADS) {
            int k = q >> 4, i = q & 15;
            int d = kc * 32 + k;
            sm.p1.Ps[k][i] = (d < D) ? P[(long long)d * 16 + i] : 0.0f;
        }
        __syncthreads();
#pragma unroll 4
        for (int k = 0; k < 32; k++) {
            float xv = sm.p1.xs[rl][k];
            const float4* pr = (const float4*)&sm.p1.Ps[k][0];
#pragma unroll
            for (int i4 = 0; i4 < 4; i4++) {
                float4 p = pr[i4];
                acc[4 * i4]     = fmaf(xv, p.x, acc[4 * i4]);
                acc[4 * i4 + 1] = fmaf(xv, p.y, acc[4 * i4 + 1]);
                acc[4 * i4 + 2] = fmaf(xv, p.z, acc[4 * i4 + 2]);
                acc[4 * i4 + 3] = fmaf(xv, p.w, acc[4 * i4 + 3]);
            }
        }
        __syncthreads();
    }

    float best = -FLT_MAX; int bi = 0x7FFFFFFF;
    for (int c0 = 0; c0 < V; c0 += CHUNK) {
        const int cnt = (V - c0 < CHUNK) ? (V - c0) : CHUNK;
#pragma unroll
        for (int q = t; q < CHUNK * 16; q += THREADS) {
            int j = q >> 4, i = q & 15;
            sm.cbs[j][i] = (j < cnt) ? CB[(long long)(c0 + j) * 16 + i] : 0.0f;
        }
        __syncthreads();
        const int jbase = half * 128;
#pragma unroll 2
        for (int jj = 0; jj < 128; jj++) {
            const int j = jbase + jj;
            const float4* cb = (const float4*)&sm.cbs[j][0];
            float s0 = 0, s1 = 0, s2 = 0, s3 = 0;
#pragma unroll
            for (int i4 = 0; i4 < 4; i4++) {
                float4 c = cb[i4];
                s0 = fmaf(acc[4 * i4],     c.x, s0);
                s1 = fmaf(acc[4 * i4 + 1], c.y, s1);
                s2 = fmaf(acc[4 * i4 + 2], c.z, s2);
                s3 = fmaf(acc[4 * i4 + 3], c.w, s3);
            }
            float s = (s0 + s1) + (s2 + s3);
            if (c0 + j < V && s > best) { best = s; bi = c0 + j; }
        }
        __syncthreads();
    }

    sm.p3.sv[t] = best; sm.p3.si[t] = bi;
    __syncthreads();
    if (t < 128) {
        int row = row0 + t;
        if (row < N) {
            float slo = sm.p3.sv[t], shi = sm.p3.sv[t + 128];
            int   ilo = sm.p3.si[t], ihi = sm.p3.si[t + 128];
            int win = (shi > slo || (shi == slo && ihi < ilo)) ? ihi : ilo;
            out[row] = (float)win;
        }
    }
}

__global__ void rpq_generic(const float* __restrict__ x, const float* __restrict__ P,
                            const float* __restrict__ CB, float* __restrict__ out,
                            int N, int D, int V, int cbd) {
    int row = blockIdx.x * blockDim.x + threadIdx.x;
    if (row >= N) return;
    float acc[64];
    for (int i = 0; i < cbd; i++) acc[i] = 0.0f;
    for (int d = 0; d < D; d++) {
        float xv = x[(long long)row * D + d];
        for (int i = 0; i < cbd; i++) acc[i] = fmaf(xv, P[(long long)d * cbd + i], acc[i]);
    }
    float best = -FLT_MAX; int bi = 0;
    for (int j = 0; j < V; j++) {
        float s = 0.0f;
        for (int i = 0; i < cbd; i++) s = fmaf(acc[i], CB[(long long)j * cbd + i], s);
        if (s > best) { best = s; bi = j; }
    }
    out[row] = (float)bi;
}

// ============================================================================
extern "C" void kernel_launch(void* const* d_in, const int* in_sizes, int n_in,
                              void* d_out, int out_size) {
    const float* x  = (const float*)d_in[0];
    const float* P  = (n_in > 1) ? (const float*)d_in[1] : nullptr;
    const float* CB = (n_in > 2) ? (const float*)d_in[2] : nullptr;
    long long N = out_size, D = 512, CBD = 16, V = 8192;

    if (n_in >= 3 && out_size > 0) {
        int order[3] = {0, 1, 2};
        for (int a = 0; a < 2; a++)
            for (int b = a + 1; b < 3; b++)
                if ((long long)in_sizes[order[b]] > (long long)in_sizes[order[a]]) {
                    int tmp = order[a]; order[a] = order[b]; order[b] = tmp;
                }
        long long sx = in_sizes[order[0]];
        long long sc = in_sizes[order[1]];
        long long sp = in_sizes[order[2]];
        if (sx % N == 0) {
            long long d = sx / N;
            if (d > 0 && sp % d == 0) {
                long long cbd = sp / d;
                if (cbd > 0 && cbd <= 64 && sc % cbd == 0) {
                    long long v = sc / cbd;
                    if (v > 0 && d * cbd == sp && v * cbd == sc && N * d == sx) {
                        D = d; CBD = cbd; V = v;
                        x  = (const float*)d_in[order[0]];
                        CB = (const float*)d_in[order[1]];
                        P  = (const float*)d_in[order[2]];
                    }
                }
            }
        }
    }

    float* out = (float*)d_out;
    int Ni = (int)N, Di = (int)D, Vi = (int)V;

    const bool fast = (CBD == 16) && (Ni % 512 == 0) && (Vi % CHUNK == 0) &&
                      (Di % 32 == 0) && (Di <= MAXD) && (Ni <= MAXN) &&
                      (Vi <= MAXV) && ((Vi / CHUNK) <= SPLITS) && (Vi >= CHUNK);

    if (fast) {
        const int nsplit    = Vi / CHUNK;
        const int rowpairs  = Ni / 2;
        const int rowblocks = rowpairs / THREADS;    // Ni % 512 == 0 -> integer
        proj_splitD<<<dim3(Ni / 128, 2), 128>>>(x, P, Ni, Di);
        argmax_partial<<<dim3(rowblocks, nsplit), THREADS>>>(CB, Ni, Vi);
        argmax_reduce<<<(Ni + 255) / 256, 256>>>(out, Ni, nsplit);
        return;
    }

    if (CBD == 16) {
        rpq_fused16<<<(Ni + 127) / 128, THREADS>>>(x, P, CB, out, Ni, Di, Vi);
    } else {
        rpq_generic<<<(Ni + 255) / 256, 256>>>(x, P, CB, out, Ni, Di, Vi, (int)CBD);
    }
}